// round 5
// baseline (speedup 1.0000x reference)
#include <cuda_runtime.h>
#include <cuda_fp16.h>

// Fixed problem shapes
#define N_NODES   2048
#define N_CHILD   4096
#define NNZ_PER   32768
#define NNZ_TOT   (2 * NNZ_PER)
#define G         8                 // samples per compute block
#define NTHREADS  1024
#define NWARPS    (NTHREADS / 32)   // 32
#define NGROUPS   (N_NODES / 32)    // 64 row-groups
#define MAXPAD    160               // >> Poisson(32) group max; mult of 4
#define PAD_ENTRIES (NGROUPS * 32 * MAXPAD)

// ---------------- static device scratch -------------------------------------
// SELL-32, 4-packed: group g, lane l, entry j lives at
//   g*32*MAXPAD + (j>>2)*128 + l*4 + (j&3)
// -> each lane's 4 consecutive entries are one uint4 (LDG.128), warp reads
//    4 consecutive 128B lines per iteration (fully coalesced).
__device__ unsigned g_pad[PAD_ENTRIES];  // (col<<16)|fp16(exp(w)), 0 = pad
__device__ int   g_fill[N_NODES];
__device__ int   g_grouplen[NGROUPS];    // uint4 iterations = ceil(maxfill/4)
__device__ float g_z[N_NODES];
__device__ float g_logz[N_NODES];

// ---------------- prep kernels ----------------------------------------------
__global__ void k_zero() {
    int i = blockIdx.x * blockDim.x + threadIdx.x;
    int stride = gridDim.x * blockDim.x;
    uint4* p4 = (uint4*)g_pad;
    for (int k = i; k < PAD_ENTRIES / 4; k += stride)
        p4[k] = make_uint4(0u, 0u, 0u, 0u);
    if (i < N_NODES) { g_fill[i] = 0; g_z[i] = 0.f; }
}

__global__ void k_scatter(const int* __restrict__ r0, const int* __restrict__ c0,
                          const float* __restrict__ d0,
                          const int* __restrict__ r1, const int* __restrict__ c1,
                          const float* __restrict__ d1) {
    int k = blockIdx.x * blockDim.x + threadIdx.x;
    if (k >= NNZ_TOT) return;
    int row, col; float w;
    if (k < NNZ_PER) { row = r0[k]; col = c0[k];                   w = d0[k]; }
    else { int j = k - NNZ_PER; row = r1[j]; col = c1[j] + N_CHILD; w = d1[j]; }
    float ew = __expf(w);
    atomicAdd(&g_z[row], ew);
    int j = atomicAdd(&g_fill[row], 1);
    if (j < MAXPAD) {
        int g = row >> 5, lane = row & 31;
        int pos = g * (32 * MAXPAD) + (j >> 2) * 128 + lane * 4 + (j & 3);
        unsigned h = (unsigned)__half_as_ushort(__float2half_rn(ew));
        g_pad[pos] = ((unsigned)col << 16) | h;
    }
}

__global__ void k_finalize() {
    int r = blockIdx.x * blockDim.x + threadIdx.x;
    if (r >= N_NODES) return;
    g_logz[r] = __logf(g_z[r]);
    int f = min(g_fill[r], MAXPAD);
    #pragma unroll
    for (int o = 16; o; o >>= 1)
        f = max(f, __shfl_xor_sync(0xFFFFFFFFu, f, o));
    if ((threadIdx.x & 31) == 0) g_grouplen[r >> 5] = (f + 3) >> 2;
}

// ---------------- main compute kernel ----------------------------------------
// One block = G=8 samples; exp(ll) as half8 (uint4) per merged column in
// 128 KB smem (1 CTA / SM, 32 warps). One warp = one 32-row group per pass;
// each SELL entry (1 uint per lane, LDG.128 packs 4) is decoded once and its
// smem gather (LDS.128) feeds 8 samples; fp32 register accumulation.
__global__ void __launch_bounds__(NTHREADS, 1)
k_main(const float* __restrict__ ll0, const float* __restrict__ ll1,
       float* __restrict__ out) {
    extern __shared__ uint4 ell[];   // [2 * N_CHILD] half8 entries
    const int tid = threadIdx.x;
    const long long s0 = (long long)blockIdx.x * G;

    // load + exponentiate 8 ll rows per merged column, pack to half8
    for (int i = tid; i < 2 * N_CHILD; i += NTHREADS) {
        const float* p = (i < N_CHILD) ? (ll0 + s0 * N_CHILD + i)
                                       : (ll1 + s0 * N_CHILD + (i - N_CHILD));
        float e0 = __expf(p[0]);
        float e1 = __expf(p[N_CHILD]);
        float e2 = __expf(p[2 * N_CHILD]);
        float e3 = __expf(p[3 * N_CHILD]);
        float e4 = __expf(p[4 * N_CHILD]);
        float e5 = __expf(p[5 * N_CHILD]);
        float e6 = __expf(p[6 * N_CHILD]);
        float e7 = __expf(p[7 * N_CHILD]);
        __half2 h0 = __floats2half2_rn(e0, e1);
        __half2 h1 = __floats2half2_rn(e2, e3);
        __half2 h2 = __floats2half2_rn(e4, e5);
        __half2 h3 = __floats2half2_rn(e6, e7);
        ell[i] = make_uint4(*(unsigned*)&h0, *(unsigned*)&h1,
                            *(unsigned*)&h2, *(unsigned*)&h3);
    }
    __syncthreads();

    const int warp = tid >> 5, lane = tid & 31;
    #pragma unroll
    for (int pass = 0; pass < NGROUPS / NWARPS; ++pass) {   // 2 passes
        const int g    = warp + pass * NWARPS;
        const int lenb = g_grouplen[g];
        const uint4* __restrict__ p4 =
            (const uint4*)(g_pad + g * (32 * MAXPAD)) + lane;
        float acc[8];
        #pragma unroll
        for (int q = 0; q < 8; ++q) acc[q] = 0.f;

        #pragma unroll 2
        for (int jb = 0; jb < lenb; ++jb) {
            uint4 e4v = __ldg(&p4[jb * 32]);
            #pragma unroll
            for (int q = 0; q < 4; ++q) {
                unsigned e = (q == 0) ? e4v.x : (q == 1) ? e4v.y
                           : (q == 2) ? e4v.z : e4v.w;
                float w = __half2float(__ushort_as_half((unsigned short)(e & 0xFFFFu)));
                uint4 hv = ell[e >> 16];
                float2 v0 = __half22float2(*(__half2*)&hv.x);
                float2 v1 = __half22float2(*(__half2*)&hv.y);
                float2 v2 = __half22float2(*(__half2*)&hv.z);
                float2 v3 = __half22float2(*(__half2*)&hv.w);
                acc[0] = fmaf(v0.x, w, acc[0]);
                acc[1] = fmaf(v0.y, w, acc[1]);
                acc[2] = fmaf(v1.x, w, acc[2]);
                acc[3] = fmaf(v1.y, w, acc[3]);
                acc[4] = fmaf(v2.x, w, acc[4]);
                acc[5] = fmaf(v2.y, w, acc[5]);
                acc[6] = fmaf(v3.x, w, acc[6]);
                acc[7] = fmaf(v3.y, w, acc[7]);
            }
        }
        const int r = g * 32 + lane;
        float lz = g_logz[r];
        float* o = out + s0 * N_NODES + r;
        #pragma unroll
        for (int q = 0; q < 8; ++q)
            o[q * N_NODES] = __logf(acc[q]) - lz;
    }
}

// ---------------- launch ------------------------------------------------------
extern "C" void kernel_launch(void* const* d_in, const int* in_sizes, int n_in,
                              void* d_out, int out_size) {
    const float* ll0 = (const float*)d_in[0];
    const float* ll1 = (const float*)d_in[1];
    const float* w0d = (const float*)d_in[2];
    const float* w1d = (const float*)d_in[3];
    const int*   w0r = (const int*)d_in[4];
    const int*   w0c = (const int*)d_in[5];
    const int*   w1r = (const int*)d_in[6];
    const int*   w1c = (const int*)d_in[7];
    float* out = (float*)d_out;

    const int S = in_sizes[0] / N_CHILD;   // 4096
    const int nblocks = S / G;             // 512

    const int smem_bytes = 2 * N_CHILD * (int)sizeof(uint4);  // 128 KB
    cudaFuncSetAttribute(k_main, cudaFuncAttributeMaxDynamicSharedMemorySize,
                         smem_bytes);

    k_zero<<<512, 256>>>();
    k_scatter<<<(NNZ_TOT + 255) / 256, 256>>>(w0r, w0c, w0d, w1r, w1c, w1d);
    k_finalize<<<(N_NODES + 255) / 256, 256>>>();
    k_main<<<nblocks, NTHREADS, smem_bytes>>>(ll0, ll1, out);
}

// round 6
// speedup vs baseline: 1.1267x; 1.1267x over previous
#include <cuda_runtime.h>
#include <cuda_fp16.h>

// Fixed problem shapes
#define N_NODES   2048
#define N_CHILD   4096
#define NNZ_PER   32768
#define NNZ_TOT   (2 * NNZ_PER)
#define G         4                 // samples per compute block
#define NTHREADS  512
#define NWARPS    (NTHREADS / 32)   // 16
#define NGROUPS   (N_NODES / 32)    // 64 row-groups (one warp each)
#define MAXPAD    96                // group max ~48; 2x margin; mult of 4
#define PAD_ENTRIES (NGROUPS * 32 * MAXPAD)

// ---------------- static device scratch -------------------------------------
// SELL-32, 4-packed: group g, lane l, entry j lives at
//   g*32*MAXPAD + (j>>2)*128 + l*4 + (j&3)
// -> each lane's 4 consecutive entries are one uint4 (LDG.128), warp reads
//    4 consecutive 128B lines per iteration (fully coalesced).
__device__ unsigned g_pad[PAD_ENTRIES];  // (col<<16)|fp16(exp(w)), 0 = pad
__device__ int   g_fill[N_NODES];
__device__ int   g_grouplen[NGROUPS];    // uint4 iterations = ceil(maxfill/4)
__device__ float g_z[N_NODES];
__device__ float g_logz[N_NODES];

// ---------------- prep kernels ----------------------------------------------
__global__ void k_zero() {
    int i = blockIdx.x * blockDim.x + threadIdx.x;
    int stride = gridDim.x * blockDim.x;
    uint4* p4 = (uint4*)g_pad;
    for (int k = i; k < PAD_ENTRIES / 4; k += stride)
        p4[k] = make_uint4(0u, 0u, 0u, 0u);
    if (i < N_NODES) { g_fill[i] = 0; g_z[i] = 0.f; }
}

__global__ void k_scatter(const int* __restrict__ r0, const int* __restrict__ c0,
                          const float* __restrict__ d0,
                          const int* __restrict__ r1, const int* __restrict__ c1,
                          const float* __restrict__ d1) {
    int k = blockIdx.x * blockDim.x + threadIdx.x;
    if (k >= NNZ_TOT) return;
    int row, col; float w;
    if (k < NNZ_PER) { row = r0[k]; col = c0[k];                   w = d0[k]; }
    else { int j = k - NNZ_PER; row = r1[j]; col = c1[j] + N_CHILD; w = d1[j]; }
    float ew = __expf(w);
    atomicAdd(&g_z[row], ew);
    int j = atomicAdd(&g_fill[row], 1);
    if (j < MAXPAD) {
        int g = row >> 5, lane = row & 31;
        int pos = g * (32 * MAXPAD) + (j >> 2) * 128 + lane * 4 + (j & 3);
        unsigned h = (unsigned)__half_as_ushort(__float2half_rn(ew));
        g_pad[pos] = ((unsigned)col << 16) | h;
    }
}

__global__ void k_finalize() {
    int r = blockIdx.x * blockDim.x + threadIdx.x;
    if (r >= N_NODES) return;
    g_logz[r] = __logf(g_z[r]);
    int f = min(g_fill[r], MAXPAD);
    #pragma unroll
    for (int o = 16; o; o >>= 1)
        f = max(f, __shfl_xor_sync(0xFFFFFFFFu, f, o));
    if ((threadIdx.x & 31) == 0) g_grouplen[r >> 5] = (f + 3) >> 2;
}

// ---------------- main compute kernel ----------------------------------------
// One block = G=4 samples; exp(ll) as half4 in 64 KB smem -> 3 CTAs/SM,
// 48 warps/SM. One warp = one 32-row group per pass. Inner loop is software-
// pipelined: next SELL uint4 prefetched while current 4 entries are processed;
// the 4 random LDS.64 gathers are issued back-to-back before any FMA so four
// gathers are in flight per iteration. fp32 register accumulation.
__global__ void __launch_bounds__(NTHREADS, 3)
k_main(const float* __restrict__ ll0, const float* __restrict__ ll1,
       float* __restrict__ out) {
    extern __shared__ uint2 ell[];   // [2 * N_CHILD] half4 entries
    const int tid = threadIdx.x;
    const long long s0 = (long long)blockIdx.x * G;
    const float* p0 = ll0 + s0 * N_CHILD;
    const float* p1 = ll1 + s0 * N_CHILD;

    for (int i = tid; i < N_CHILD; i += NTHREADS) {
        float a0 = __expf(p0[i]);
        float a1 = __expf(p0[i + N_CHILD]);
        float a2 = __expf(p0[i + 2 * N_CHILD]);
        float a3 = __expf(p0[i + 3 * N_CHILD]);
        __half2 h01 = __floats2half2_rn(a0, a1);
        __half2 h23 = __floats2half2_rn(a2, a3);
        ell[i] = make_uint2(*(unsigned*)&h01, *(unsigned*)&h23);

        float b0 = __expf(p1[i]);
        float b1 = __expf(p1[i + N_CHILD]);
        float b2 = __expf(p1[i + 2 * N_CHILD]);
        float b3 = __expf(p1[i + 3 * N_CHILD]);
        __half2 g01 = __floats2half2_rn(b0, b1);
        __half2 g23 = __floats2half2_rn(b2, b3);
        ell[N_CHILD + i] = make_uint2(*(unsigned*)&g01, *(unsigned*)&g23);
    }
    __syncthreads();

    const int warp = tid >> 5, lane = tid & 31;
    #pragma unroll
    for (int pass = 0; pass < NGROUPS / NWARPS; ++pass) {   // 4 passes
        const int g    = warp + pass * NWARPS;
        const int lenb = g_grouplen[g];
        const uint4* __restrict__ p4 =
            (const uint4*)(g_pad + g * (32 * MAXPAD)) + lane;
        float4 acc = make_float4(0.f, 0.f, 0.f, 0.f);

        uint4 cur = make_uint4(0u, 0u, 0u, 0u);
        if (lenb > 0) cur = __ldg(p4);

        for (int jb = 0; jb < lenb; ++jb) {
            uint4 nxt = make_uint4(0u, 0u, 0u, 0u);
            if (jb + 1 < lenb) nxt = __ldg(&p4[(jb + 1) * 32]);

            // issue all four gathers before consuming any
            uint2 hv0 = ell[cur.x >> 16];
            uint2 hv1 = ell[cur.y >> 16];
            uint2 hv2 = ell[cur.z >> 16];
            uint2 hv3 = ell[cur.w >> 16];
            float w0 = __half2float(__ushort_as_half((unsigned short)(cur.x & 0xFFFFu)));
            float w1 = __half2float(__ushort_as_half((unsigned short)(cur.y & 0xFFFFu)));
            float w2 = __half2float(__ushort_as_half((unsigned short)(cur.z & 0xFFFFu)));
            float w3 = __half2float(__ushort_as_half((unsigned short)(cur.w & 0xFFFFu)));

            float2 a01 = __half22float2(*(__half2*)&hv0.x);
            float2 a23 = __half22float2(*(__half2*)&hv0.y);
            acc.x = fmaf(a01.x, w0, acc.x);
            acc.y = fmaf(a01.y, w0, acc.y);
            acc.z = fmaf(a23.x, w0, acc.z);
            acc.w = fmaf(a23.y, w0, acc.w);

            float2 b01 = __half22float2(*(__half2*)&hv1.x);
            float2 b23 = __half22float2(*(__half2*)&hv1.y);
            acc.x = fmaf(b01.x, w1, acc.x);
            acc.y = fmaf(b01.y, w1, acc.y);
            acc.z = fmaf(b23.x, w1, acc.z);
            acc.w = fmaf(b23.y, w1, acc.w);

            float2 c01 = __half22float2(*(__half2*)&hv2.x);
            float2 c23 = __half22float2(*(__half2*)&hv2.y);
            acc.x = fmaf(c01.x, w2, acc.x);
            acc.y = fmaf(c01.y, w2, acc.y);
            acc.z = fmaf(c23.x, w2, acc.z);
            acc.w = fmaf(c23.y, w2, acc.w);

            float2 d01 = __half22float2(*(__half2*)&hv3.x);
            float2 d23 = __half22float2(*(__half2*)&hv3.y);
            acc.x = fmaf(d01.x, w3, acc.x);
            acc.y = fmaf(d01.y, w3, acc.y);
            acc.z = fmaf(d23.x, w3, acc.z);
            acc.w = fmaf(d23.y, w3, acc.w);

            cur = nxt;
        }

        const int r = g * 32 + lane;
        float lz = g_logz[r];
        float* o = out + s0 * N_NODES + r;
        o[0]           = __logf(acc.x) - lz;
        o[N_NODES]     = __logf(acc.y) - lz;
        o[2 * N_NODES] = __logf(acc.z) - lz;
        o[3 * N_NODES] = __logf(acc.w) - lz;
    }
}

// ---------------- launch ------------------------------------------------------
extern "C" void kernel_launch(void* const* d_in, const int* in_sizes, int n_in,
                              void* d_out, int out_size) {
    const float* ll0 = (const float*)d_in[0];
    const float* ll1 = (const float*)d_in[1];
    const float* w0d = (const float*)d_in[2];
    const float* w1d = (const float*)d_in[3];
    const int*   w0r = (const int*)d_in[4];
    const int*   w0c = (const int*)d_in[5];
    const int*   w1r = (const int*)d_in[6];
    const int*   w1c = (const int*)d_in[7];
    float* out = (float*)d_out;

    const int S = in_sizes[0] / N_CHILD;   // 4096
    const int nblocks = S / G;             // 1024

    const int smem_bytes = 2 * N_CHILD * (int)sizeof(uint2);  // 64 KB
    cudaFuncSetAttribute(k_main, cudaFuncAttributeMaxDynamicSharedMemorySize,
                         smem_bytes);

    k_zero<<<384, 256>>>();
    k_scatter<<<(NNZ_TOT + 255) / 256, 256>>>(w0r, w0c, w0d, w1r, w1c, w1d);
    k_finalize<<<(N_NODES + 255) / 256, 256>>>();
    k_main<<<nblocks, NTHREADS, smem_bytes>>>(ll0, ll1, out);
}